// round 12
// baseline (speedup 1.0000x reference)
#include <cuda_runtime.h>
#include <math.h>

#define B      64
#define T      200
#define Q      4096
#define Q2     (2*Q)
#define TM1    (T-1)            // 199
#define NROW   (B*TM1)          // 12736
#define NPROBE 12               // probe rows s = 16, 32, ..., 192
#define NPB    (B*NPROBE)       // 768 probe blocks
#define NBLK   (NPB + NROW)     // 13504 blocks in the fused launch

// Scratch (no device allocation allowed)
__device__ float    g_p[NROW];
__device__ float    g_a[NROW];
__device__ int      g_flag[NROW];
__device__ unsigned g_pb[B];     // bits 0..11 probe-done, bits 16..27 probe-valid
__device__ float    g_lossb[B];
__device__ int      g_count;     // used only by the 64-block epilogue

__device__ __forceinline__ int check4(float4 v, int vi, int f)
{
    if (v.x != 0.0f) f = vi * 4 + 0;
    if (v.y != 0.0f) f = vi * 4 + 1;
    if (v.z != 0.0f) f = vi * 4 + 2;
    if (v.w != 0.0f) f = vi * 4 + 3;
    return f;
}

__device__ __forceinline__ void store_row(const float* __restrict__ pred,
                                          int b, int t, int j)
{
    if (threadIdx.x == 0) {
        float p = 0.0f, a = 0.0f;
        int fl = 0;
        if (j >= 0) {
            const int q = j & (Q - 1);
            a  = (j < Q) ? 1.0f : 0.0f;
            p  = __ldg(pred + ((size_t)b * T + t) * (size_t)Q + q);
            fl = 1;
        }
        const int row = b * TM1 + t;
        g_p[row]    = p;
        g_a[row]    = a;
        g_flag[row] = fl;
    }
}

// ---------------------------------------------------------------------------
// Four-stage row scan: 8 KB per stage (2 float4/thread in flight; block-level
// window 8 KB x 8 blocks/SM stays far above the latency cliff).
// E[bytes] = 20 KB for a uniform one-hot (vs 22 KB for 16/8/8).
// ---------------------------------------------------------------------------
__device__ __forceinline__ int scan_row4(const float* __restrict__ batch,
                                         int b, int s)
{
    const float4* __restrict__ base =
        reinterpret_cast<const float4*>(batch + ((size_t)b * T + s) * (size_t)Q2);
    const int tid = threadIdx.x;

    __shared__ int s_idx;
    if (tid == 0) s_idx = -1;
    __syncthreads();

    #pragma unroll
    for (int st = 0; st < 4; ++st) {
        const int o0 = st * 512 + tid;           // 512 float4 per stage
        const int o1 = o0 + 256;
        float4 v0 = base[o0];
        float4 v1 = base[o1];
        int f = -1;
        f = check4(v0, o0, f);
        f = check4(v1, o1, f);
        if (f >= 0) s_idx = f;
        if (st < 3) {
            if (__syncthreads_or(f >= 0)) return s_idx;
        } else {
            __syncthreads();
        }
    }
    return s_idx;
}

// ---------------------------------------------------------------------------
// Fused kernel: bids [0,768) probe; bids [768, NBLK) scan, t-MAJOR order
// (wave 1 = small-s rows of all batches: no probe dependency, ~all valid).
// NO gpu-scope fences / release atomics (R4+R6: per-block gpu-release at
// grid ~13k caps the chip at ~2.2 TB/s). Publish = plain atomicOr (L2-point);
// poll = ld.global.cg, bounded spin + full-scan fallback (deadlock-free).
// ---------------------------------------------------------------------------
__global__ __launch_bounds__(256)
void fused_kernel(const float* __restrict__ pred,
                  const float* __restrict__ batch)
{
    const int bid = blockIdx.x;
    const int tid = threadIdx.x;

    if (bid < NPB) {
        // ---- probe block: full row, MLP=8, one barrier ----
        const int b = bid / NPROBE;
        const int k = bid % NPROBE;
        const int s = 16 * (k + 1);
        const float4* __restrict__ base =
            reinterpret_cast<const float4*>(batch + ((size_t)b * T + s) * (size_t)Q2);

        __shared__ int s_idx;
        if (tid == 0) s_idx = -1;
        __syncthreads();

        float4 v[8];
        #pragma unroll
        for (int c = 0; c < 8; ++c) v[c] = base[c * 256 + tid];
        int f = -1;
        #pragma unroll
        for (int c = 0; c < 8; ++c) f = check4(v[c], c * 256 + tid, f);
        if (f >= 0) s_idx = f;
        __syncthreads();

        store_row(pred, b, s - 1, s_idx);
        if (tid == 0) {
            const unsigned bits =
                (1u << k) | ((s_idx >= 0) ? (1u << (16 + k)) : 0u);
            atomicOr(&g_pb[b], bits);            // plain L2 publish, no fence
        }
        return;
    }

    // ---- scan block (t-major: consecutive bids sweep all batches at one t) ----
    const int sb = bid - NPB;                    // 0 .. NROW-1
    const int t  = sb / B;                       // 0 .. 198
    const int b  = sb % B;
    const int s  = t + 1;
    if (s <= 192 && (s & 15) == 0) return;       // handled by a probe block

    // Partial-info wait: only probes k with 16(k+1) <= s govern this row.
    const int kmax = min(s >> 4, NPROBE);
    unsigned v = 0;
    if (kmax > 0) {
        const unsigned need = (1u << kmax) - 1u;
        __shared__ unsigned s_v;
        if (tid == 0) {
            unsigned w = 0;
            int it = 0;
            do {
                asm volatile("ld.global.cg.u32 %0, [%1];"
                             : "=r"(w) : "l"(&g_pb[b]) : "memory");
                if ((w & need) == need) break;
                __nanosleep(64);
            } while (++it < 20000);
            s_v = ((w & need) == need) ? w : 0u; // timeout => no info
        }
        __syncthreads();
        v = s_v;
    }

    int ub = 200;
    #pragma unroll
    for (int k = NPROBE - 1; k >= 0; --k)
        if (((v >> k) & 1u) && !((v >> (16 + k)) & 1u)) ub = 16 * (k + 1);

    if (s >= ub) {                               // provably all-zero: no reads
        store_row(pred, b, t, -1);
        return;
    }
    const int j = scan_row4(batch, b, s);
    store_row(pred, b, t, j);
}

// ---------------------------------------------------------------------------
// Epilogue, grid=64, PDL: scalar loads issued BEFORE griddepcontrol.wait so
// their latency overlaps the wait; the wait orders all g_* reads after the
// fused kernel's completion.
// Output layout: [0]=loss, [1..1+N)=p*maskf, [1+N..1+2N)=a*maskf,
//                [1+2N..1+3N)=mask, N = B*TM1.
// ---------------------------------------------------------------------------
__global__ __launch_bounds__(256)
void epilogue_kernel(const int* __restrict__ isTestP,
                     const int* __restrict__ tslP,
                     float* __restrict__ d_out)
{
    // Inputs are harness-owned and constant across the launch: read them
    // before the PDL wait to overlap their L2 round trip with the wait.
    const int isTest = *isTestP;
    const int tsl    = *tslP;

    asm volatile("griddepcontrol.wait;" ::: "memory");   // wait for fused_kernel

    const int b   = blockIdx.x;
    const int tid = threadIdx.x;

    float p = 0.0f, a = 0.0f;
    int myLast = -1;
    if (tid < TM1) {
        const int idx = b * TM1 + tid;
        p = g_p[idx];
        a = g_a[idx];
        if (g_flag[idx] > 0) myLast = tid;
    }

    __shared__ int s_i[256];
    s_i[tid] = myLast;
    __syncthreads();
    #pragma unroll
    for (int off = 128; off > 0; off >>= 1) {
        if (tid < off) s_i[tid] = max(s_i[tid], s_i[tid + off]);
        __syncthreads();
    }
    const int last = max(s_i[0], 0);

    int start = 0;
    if (isTest) {
        const int length = last + 1;
        start = (length > tsl) ? (length - tsl) : 0;
    }

    const bool  m     = (tid < TM1) && (tid >= start) && (tid <= last);
    const float maskf = m ? 1.0f : 0.0f;
    const float cnt   = (float)(last - start + 1);

    float bce = 0.0f;
    if (tid < TM1) {
        const float logp = fmaxf(logf(p), -100.0f);
        const float l1mp = fmaxf(log1pf(-p), -100.0f);
        bce = -(a * logp + (1.0f - a) * l1mp);

        const int idx = b * TM1 + tid;
        d_out[1 + idx]            = p * maskf;
        d_out[1 + NROW + idx]     = a * maskf;
        d_out[1 + 2 * NROW + idx] = maskf;
    }

    __shared__ float s_f[256];
    s_f[tid] = bce * maskf;
    __syncthreads();
    #pragma unroll
    for (int off = 128; off > 0; off >>= 1) {
        if (tid < off) s_f[tid] += s_f[tid + off];
        __syncthreads();
    }

    __shared__ bool s_last;
    if (tid == 0) {
        g_lossb[b] = s_f[0] / cnt;
        g_pb[b]    = 0u;                         // reset for next replay
        __threadfence();
        s_last = (atomicAdd(&g_count, 1) == B - 1);
    }
    __syncthreads();

    if (s_last) {
        __shared__ float s2[64];
        if (tid < B) s2[tid] = g_lossb[tid];
        __syncthreads();
        #pragma unroll
        for (int off = 32; off > 0; off >>= 1) {
            if (tid < off) s2[tid] += s2[tid + off];
            __syncthreads();
        }
        if (tid == 0) {
            d_out[0] = s2[0];
            g_count  = 0;                        // reset for next replay
        }
    }
}

extern "C" void kernel_launch(void* const* d_in, const int* in_sizes, int n_in,
                              void* d_out, int out_size)
{
    const float* pred  = (const float*)d_in[0];
    const float* batch = (const float*)d_in[1];
    const int*   isT   = (const int*)d_in[2];
    const int*   tsl   = (const int*)d_in[3];
    float*       out   = (float*)d_out;

    fused_kernel<<<NBLK, 256>>>(pred, batch);

    // Epilogue with programmatic dependent launch.
    cudaLaunchConfig_t cfg = {};
    cfg.gridDim  = dim3(B, 1, 1);
    cfg.blockDim = dim3(256, 1, 1);
    cfg.stream   = 0;
    cudaLaunchAttribute attr[1];
    attr[0].id = cudaLaunchAttributeProgrammaticStreamSerialization;
    attr[0].val.programmaticStreamSerializationAllowed = 1;
    cfg.attrs    = attr;
    cfg.numAttrs = 1;
    cudaLaunchKernelEx(&cfg, epilogue_kernel, isT, tsl, out);
}

// round 13
// speedup vs baseline: 1.0090x; 1.0090x over previous
#include <cuda_runtime.h>
#include <math.h>

#define B      64
#define T      200
#define Q      4096
#define Q2     (2*Q)
#define TM1    (T-1)            // 199
#define NROW   (B*TM1)          // 12736
#define NPROBE 12               // probe rows s = 16, 32, ..., 192
#define NPB    (B*NPROBE)       // 768 probe blocks
#define NBLK   (NPB + NROW)     // 13504 blocks in the fused launch

// Scratch (no device allocation allowed)
__device__ float    g_p[NROW];
__device__ float    g_a[NROW];
__device__ int      g_flag[NROW];
__device__ unsigned g_pb[B];     // bits 0..11 probe-done, bits 16..27 probe-valid
__device__ float    g_sum[B];    // fast path: per-batch masked BCE sum
__device__ int      g_cnt[B];    // fast path: per-batch flagged count
__device__ float    g_lossb[B];  // general path only
__device__ int      g_count;     // general path only

__device__ __forceinline__ int check4(float4 v, int vi, int f)
{
    if (v.x != 0.0f) f = vi * 4 + 0;
    if (v.y != 0.0f) f = vi * 4 + 1;
    if (v.z != 0.0f) f = vi * 4 + 2;
    if (v.w != 0.0f) f = vi * 4 + 3;
    return f;
}

// ---------------------------------------------------------------------------
// Row finalization. Thread 0 of the owning block resolves (p, a, flag).
// Fast path (isTest==0): flags are a prefix => maskf==flag, so the three
// output rows are final NOW; BCE accumulates via plain per-batch L2 atomics
// (199 adds/address — not the R4/R6 per-block gpu-release pattern).
// General path: stash p/a/flag for the full epilogue.
// ---------------------------------------------------------------------------
__device__ __forceinline__ void finish_row(const float* __restrict__ pred,
                                           float* __restrict__ d_out,
                                           int isTest, int b, int t, int j)
{
    if (threadIdx.x == 0) {
        float p = 0.0f, a = 0.0f;
        int fl = 0;
        if (j >= 0) {
            const int q = j & (Q - 1);
            a  = (j < Q) ? 1.0f : 0.0f;
            p  = __ldg(pred + ((size_t)b * T + t) * (size_t)Q + q);
            fl = 1;
        }
        const int row = b * TM1 + t;
        if (isTest == 0) {
            d_out[1 + row]            = p;           // p * maskf (p==0 if !fl)
            d_out[1 + NROW + row]     = a;           // a * maskf
            d_out[1 + 2 * NROW + row] = (float)fl;   // maskf
            if (fl) {
                const float logp = fmaxf(logf(p), -100.0f);
                const float l1mp = fmaxf(log1pf(-p), -100.0f);
                atomicAdd(&g_sum[b], -(a * logp + (1.0f - a) * l1mp));
                atomicAdd(&g_cnt[b], 1);
            }
        } else {
            g_p[row]    = p;
            g_a[row]    = a;
            g_flag[row] = fl;
        }
    }
}

// ---------------------------------------------------------------------------
// Four-stage row scan: 8 KB per stage (block window 8 KB x 8 blocks/SM —
// far above the R9 latency cliff). E[bytes] = 20 KB for a uniform one-hot.
// ---------------------------------------------------------------------------
__device__ __forceinline__ int scan_row4(const float* __restrict__ batch,
                                         int b, int s)
{
    const float4* __restrict__ base =
        reinterpret_cast<const float4*>(batch + ((size_t)b * T + s) * (size_t)Q2);
    const int tid = threadIdx.x;

    __shared__ int s_idx;
    if (tid == 0) s_idx = -1;
    __syncthreads();

    #pragma unroll
    for (int st = 0; st < 4; ++st) {
        const int o0 = st * 512 + tid;
        const int o1 = o0 + 256;
        float4 v0 = base[o0];
        float4 v1 = base[o1];
        int f = -1;
        f = check4(v0, o0, f);
        f = check4(v1, o1, f);
        if (f >= 0) s_idx = f;
        if (st < 3) {
            if (__syncthreads_or(f >= 0)) return s_idx;
        } else {
            __syncthreads();
        }
    }
    return s_idx;
}

// ---------------------------------------------------------------------------
// Fused kernel: bids [0,768) probe; bids [768, NBLK) scan, t-major order.
// NO gpu-scope fences / release atomics (R4+R6: per-block gpu-release at
// grid ~13k caps the chip at ~2.2 TB/s). Publish = plain atomicOr (L2-point);
// poll = ld.global.cg, bounded spin + full-scan fallback (deadlock-free).
// ---------------------------------------------------------------------------
__global__ __launch_bounds__(256)
void fused_kernel(const float* __restrict__ pred,
                  const float* __restrict__ batch,
                  const int*   __restrict__ isTestP,
                  float*       __restrict__ d_out)
{
    const int bid    = blockIdx.x;
    const int tid    = threadIdx.x;
    const int isTest = __ldg(isTestP);

    if (bid < NPB) {
        // ---- probe block: full row, MLP=8, one barrier ----
        const int b = bid / NPROBE;
        const int k = bid % NPROBE;
        const int s = 16 * (k + 1);
        const float4* __restrict__ base =
            reinterpret_cast<const float4*>(batch + ((size_t)b * T + s) * (size_t)Q2);

        __shared__ int s_idx;
        if (tid == 0) s_idx = -1;
        __syncthreads();

        float4 v[8];
        #pragma unroll
        for (int c = 0; c < 8; ++c) v[c] = base[c * 256 + tid];
        int f = -1;
        #pragma unroll
        for (int c = 0; c < 8; ++c) f = check4(v[c], c * 256 + tid, f);
        if (f >= 0) s_idx = f;
        __syncthreads();

        finish_row(pred, d_out, isTest, b, s - 1, s_idx);
        if (tid == 0) {
            const unsigned bits =
                (1u << k) | ((s_idx >= 0) ? (1u << (16 + k)) : 0u);
            atomicOr(&g_pb[b], bits);            // plain L2 publish, no fence
        }
        return;
    }

    // ---- scan block (t-major: consecutive bids sweep all batches at one t) ----
    const int sb = bid - NPB;
    const int t  = sb / B;
    const int b  = sb % B;
    const int s  = t + 1;
    if (s <= 192 && (s & 15) == 0) return;       // handled by a probe block

    // Partial-info wait: only probes k with 16(k+1) <= s govern this row.
    const int kmax = min(s >> 4, NPROBE);
    unsigned v = 0;
    if (kmax > 0) {
        const unsigned need = (1u << kmax) - 1u;
        __shared__ unsigned s_v;
        if (tid == 0) {
            unsigned w = 0;
            int it = 0;
            do {
                asm volatile("ld.global.cg.u32 %0, [%1];"
                             : "=r"(w) : "l"(&g_pb[b]) : "memory");
                if ((w & need) == need) break;
                __nanosleep(64);
            } while (++it < 20000);
            s_v = ((w & need) == need) ? w : 0u; // timeout => no info
        }
        __syncthreads();
        v = s_v;
    }

    int ub = 200;
    #pragma unroll
    for (int k = NPROBE - 1; k >= 0; --k)
        if (((v >> k) & 1u) && !((v >> (16 + k)) & 1u)) ub = 16 * (k + 1);

    if (s >= ub) {                               // provably all-zero: no reads
        finish_row(pred, d_out, isTest, b, t, -1);
        return;
    }
    const int j = scan_row4(batch, b, s);
    finish_row(pred, d_out, isTest, b, t, j);
}

// ---------------------------------------------------------------------------
// Final kernel (PDL). Fast path (isTest==0): block 0 folds 64 (sum,cnt)
// pairs into the loss; other blocks just reset state. General path: full
// epilogue as before.
// Output layout: [0]=loss, [1..1+N)=p*maskf, [1+N..1+2N)=a*maskf,
//                [1+2N..1+3N)=mask, N = B*TM1.
// ---------------------------------------------------------------------------
__global__ __launch_bounds__(256)
void epilogue_kernel(const int* __restrict__ isTestP,
                     const int* __restrict__ tslP,
                     float* __restrict__ d_out)
{
    const int isTest = *isTestP;     // overlap these L2 trips with the wait
    const int tsl    = *tslP;

    asm volatile("griddepcontrol.wait;" ::: "memory");   // fused_kernel done

    const int b   = blockIdx.x;
    const int tid = threadIdx.x;

    if (isTest == 0) {
        // ---- fast path: outputs already written by fused_kernel ----
        if (tid == 0) g_pb[b] = 0u;              // reset for next replay
        if (b == 0) {
            __shared__ float s2[64];
            float lb = 0.0f;
            if (tid < B) {
                const int   c = g_cnt[tid];
                const float s = g_sum[tid];
                lb = (c > 0) ? (s / (float)c) : 0.0f;
                g_sum[tid] = 0.0f;               // reset for next replay
                g_cnt[tid] = 0;
            }
            if (tid < 64) s2[tid] = lb;
            __syncthreads();
            #pragma unroll
            for (int off = 32; off > 0; off >>= 1) {
                if (tid < off) s2[tid] += s2[tid + off];
                __syncthreads();
            }
            if (tid == 0) d_out[0] = s2[0];
        }
        return;
    }

    // ---- general path (isTest != 0) ----
    float p = 0.0f, a = 0.0f;
    int myLast = -1;
    if (tid < TM1) {
        const int idx = b * TM1 + tid;
        p = g_p[idx];
        a = g_a[idx];
        if (g_flag[idx] > 0) myLast = tid;
    }

    __shared__ int s_i[256];
    s_i[tid] = myLast;
    __syncthreads();
    #pragma unroll
    for (int off = 128; off > 0; off >>= 1) {
        if (tid < off) s_i[tid] = max(s_i[tid], s_i[tid + off]);
        __syncthreads();
    }
    const int last = max(s_i[0], 0);

    int start = 0;
    {
        const int length = last + 1;
        start = (length > tsl) ? (length - tsl) : 0;
    }

    const bool  m     = (tid < TM1) && (tid >= start) && (tid <= last);
    const float maskf = m ? 1.0f : 0.0f;
    const float cnt   = (float)(last - start + 1);

    float bce = 0.0f;
    if (tid < TM1) {
        const float logp = fmaxf(logf(p), -100.0f);
        const float l1mp = fmaxf(log1pf(-p), -100.0f);
        bce = -(a * logp + (1.0f - a) * l1mp);

        const int idx = b * TM1 + tid;
        d_out[1 + idx]            = p * maskf;
        d_out[1 + NROW + idx]     = a * maskf;
        d_out[1 + 2 * NROW + idx] = maskf;
    }

    __shared__ float s_f[256];
    s_f[tid] = bce * maskf;
    __syncthreads();
    #pragma unroll
    for (int off = 128; off > 0; off >>= 1) {
        if (tid < off) s_f[tid] += s_f[tid + off];
        __syncthreads();
    }

    __shared__ bool s_last;
    if (tid == 0) {
        g_lossb[b] = s_f[0] / cnt;
        g_pb[b]    = 0u;                         // reset for next replay
        __threadfence();
        s_last = (atomicAdd(&g_count, 1) == B - 1);
    }
    __syncthreads();

    if (s_last) {
        __shared__ float s2[64];
        if (tid < B) s2[tid] = g_lossb[tid];
        __syncthreads();
        #pragma unroll
        for (int off = 32; off > 0; off >>= 1) {
            if (tid < off) s2[tid] += s2[tid + off];
            __syncthreads();
        }
        if (tid == 0) {
            d_out[0] = s2[0];
            g_count  = 0;                        // reset for next replay
        }
    }
}

extern "C" void kernel_launch(void* const* d_in, const int* in_sizes, int n_in,
                              void* d_out, int out_size)
{
    const float* pred  = (const float*)d_in[0];
    const float* batch = (const float*)d_in[1];
    const int*   isT   = (const int*)d_in[2];
    const int*   tsl   = (const int*)d_in[3];
    float*       out   = (float*)d_out;

    fused_kernel<<<NBLK, 256>>>(pred, batch, isT, out);

    // Final kernel with programmatic dependent launch.
    cudaLaunchConfig_t cfg = {};
    cfg.gridDim  = dim3(B, 1, 1);
    cfg.blockDim = dim3(256, 1, 1);
    cfg.stream   = 0;
    cudaLaunchAttribute attr[1];
    attr[0].id = cudaLaunchAttributeProgrammaticStreamSerialization;
    attr[0].val.programmaticStreamSerializationAllowed = 1;
    cfg.attrs    = attr;
    cfg.numAttrs = 1;
    cudaLaunchKernelEx(&cfg, epilogue_kernel, isT, tsl, out);
}